// round 12
// baseline (speedup 1.0000x reference)
#include <cuda_runtime.h>
#include <cstdint>

#define THREADS 256
#define F_TILE  128
#define HALF    257
#define NMELS   64
#define FFT     512
#define KPAD    272            // 17 x 16
#define NKSTEP  17
#define PAIRS   136            // KPAD/2
#define STRIDE  280            // smem row stride in bf16 (560B, 16B-aligned)

#define SM_AHI  0
#define SM_ALO  (F_TILE * STRIDE * 2)              //  71680
#define SM_BHI  (2 * F_TILE * STRIDE * 2)          // 143360
#define SM_BLO  (SM_BHI + NMELS * STRIDE * 2)      // 179200
#define SM_TOTAL (SM_BLO + NMELS * STRIDE * 2)     // 215040

__device__ __forceinline__ uint32_t smem_u32(const void* p) {
    uint32_t a;
    asm("{ .reg .u64 t; cvta.to.shared.u64 t, %1; cvt.u32.u64 %0, t; }" : "=r"(a) : "l"(p));
    return a;
}

// pack {lo at k, hi at k+1} into bf16x2 (first arg -> low half)
__device__ __forceinline__ uint32_t pack_bf16x2(float lo, float hi) {
    uint32_t r;
    asm("cvt.rn.bf16x2.f32 %0, %1, %2;" : "=r"(r) : "f"(hi), "f"(lo));
    return r;
}

__device__ __forceinline__ void ldsm_x4(uint32_t* r, uint32_t addr) {
    asm volatile("ldmatrix.sync.aligned.m8n8.x4.shared.b16 {%0,%1,%2,%3}, [%4];"
                 : "=r"(r[0]), "=r"(r[1]), "=r"(r[2]), "=r"(r[3]) : "r"(addr));
}

__device__ __forceinline__ void mma16816(float* c, const uint32_t* a, const uint32_t* b) {
    asm volatile(
        "mma.sync.aligned.m16n8k16.row.col.f32.bf16.bf16.f32 "
        "{%0,%1,%2,%3}, {%4,%5,%6,%7}, {%8,%9}, {%0,%1,%2,%3};"
        : "+f"(c[0]), "+f"(c[1]), "+f"(c[2]), "+f"(c[3])
        : "r"(a[0]), "r"(a[1]), "r"(a[2]), "r"(a[3]), "r"(b[0]), "r"(b[1]));
}

// split a pair of f32 into bf16x2 hi and bf16x2 lo words
__device__ __forceinline__ void split_pair(float m0, float m1, uint32_t& hi, uint32_t& lo) {
    hi = pack_bf16x2(m0, m1);
    float h0 = __uint_as_float(hi << 16);
    float h1 = __uint_as_float(hi & 0xFFFF0000u);
    lo = pack_bf16x2(m0 - h0, m1 - h1);
}

__global__ __launch_bounds__(THREADS, 1)
void lmfe_hmma_kernel(const float* __restrict__ x, const float* __restrict__ fb,
                      float* __restrict__ out)
{
    extern __shared__ char smem[];
    const uint32_t smem_base = smem_u32(smem);
    const int tid   = threadIdx.x;
    const int wid   = tid >> 5;
    const int lane  = tid & 31;
    const int fbase = blockIdx.x * F_TILE;

    // ---- stage A: mag = (x+1)^2, split hi/lo bf16, native K-major layout ----
    const float* xp = x + (size_t)fbase * FFT;
    #pragma unroll 4
    for (int idx = tid; idx < F_TILE * PAIRS; idx += THREADS) {
        int f = idx / PAIRS;
        int p = idx - f * PAIRS;
        float m0 = 0.f, m1 = 0.f;
        if (p < 128) {
            float2 t = *reinterpret_cast<const float2*>(xp + (size_t)f * FFT + 2 * p);
            float v0 = t.x + 1.f, v1 = t.y + 1.f;
            m0 = v0 * v0; m1 = v1 * v1;
        } else if (p == 128) {
            float v0 = xp[(size_t)f * FFT + 256] + 1.f;
            m0 = v0 * v0;                        // k=257..271 zero-padded
        }
        uint32_t hi, lo;
        split_pair(m0, m1, hi, lo);
        uint32_t off = (uint32_t)(f * STRIDE + 2 * p) * 2;
        *reinterpret_cast<uint32_t*>(smem + SM_AHI + off) = hi;
        *reinterpret_cast<uint32_t*>(smem + SM_ALO + off) = lo;
    }

    // ---- stage B: fb split hi/lo, [n][k] (col-major KxN for mma.row.col) ----
    for (int idx = tid; idx < NMELS * PAIRS; idx += THREADS) {
        int n = idx / PAIRS;
        int p = idx - n * PAIRS;
        float m0 = 0.f, m1 = 0.f;
        if (p < 128) {
            m0 = fb[n * HALF + 2 * p];
            m1 = fb[n * HALF + 2 * p + 1];
        } else if (p == 128) {
            m0 = fb[n * HALF + 256];
        }
        uint32_t hi, lo;
        split_pair(m0, m1, hi, lo);
        uint32_t off = (uint32_t)(n * STRIDE + 2 * p) * 2;
        *reinterpret_cast<uint32_t*>(smem + SM_BHI + off) = hi;
        *reinterpret_cast<uint32_t*>(smem + SM_BLO + off) = lo;
    }
    __syncthreads();

    // ---- warp tiles: 8 warps = 4 (frames) x 2 (mels); tile 32f x 32m ----
    const int m0w = (wid & 3) * 32;
    const int n0w = (wid >> 2) * 32;

    // ldmatrix lane-offset (k-invariant): same pattern for hi and lo regions
    const uint32_t a_loff =
        (uint32_t)((m0w + (lane & 15)) * STRIDE * 2) + ((lane >> 4) << 4);
    const uint32_t b_loff =
        (uint32_t)((n0w + (lane & 7) + ((lane >> 4) << 3)) * STRIDE * 2) +
        (((lane >> 3) & 1) << 4);

    const uint32_t ah_base = smem_base + SM_AHI + a_loff;
    const uint32_t al_base = smem_base + SM_ALO + a_loff;
    const uint32_t bh_base = smem_base + SM_BHI + b_loff;
    const uint32_t bl_base = smem_base + SM_BLO + b_loff;

    float acc[2][4][4];
    #pragma unroll
    for (int mb = 0; mb < 2; ++mb)
        #pragma unroll
        for (int nb = 0; nb < 4; ++nb)
            #pragma unroll
            for (int i = 0; i < 4; ++i) acc[mb][nb][i] = 0.f;

    #pragma unroll 1
    for (int ks = 0; ks < NKSTEP; ++ks) {
        const uint32_t koff = (uint32_t)ks * 32;   // 16 bf16 = 32B per k-step
        const uint32_t mstep = 16u * STRIDE * 2;
        uint32_t ah0[4], ah1[4], al0[4], al1[4], bh0[4], bh1[4], bl0[4], bl1[4];
        ldsm_x4(ah0, ah_base + koff);
        ldsm_x4(ah1, ah_base + koff + mstep);
        ldsm_x4(bh0, bh_base + koff);
        ldsm_x4(bh1, bh_base + koff + mstep);
        ldsm_x4(al0, al_base + koff);
        ldsm_x4(al1, al_base + koff + mstep);
        ldsm_x4(bl0, bl_base + koff);
        ldsm_x4(bl1, bl_base + koff + mstep);

        // chain hi*hi
        mma16816(acc[0][0], ah0, bh0);
        mma16816(acc[0][1], ah0, bh0 + 2);
        mma16816(acc[0][2], ah0, bh1);
        mma16816(acc[0][3], ah0, bh1 + 2);
        mma16816(acc[1][0], ah1, bh0);
        mma16816(acc[1][1], ah1, bh0 + 2);
        mma16816(acc[1][2], ah1, bh1);
        mma16816(acc[1][3], ah1, bh1 + 2);
        // chain hi*lo
        mma16816(acc[0][0], ah0, bl0);
        mma16816(acc[0][1], ah0, bl0 + 2);
        mma16816(acc[0][2], ah0, bl1);
        mma16816(acc[0][3], ah0, bl1 + 2);
        mma16816(acc[1][0], ah1, bl0);
        mma16816(acc[1][1], ah1, bl0 + 2);
        mma16816(acc[1][2], ah1, bl1);
        mma16816(acc[1][3], ah1, bl1 + 2);
        // chain lo*hi
        mma16816(acc[0][0], al0, bh0);
        mma16816(acc[0][1], al0, bh0 + 2);
        mma16816(acc[0][2], al0, bh1);
        mma16816(acc[0][3], al0, bh1 + 2);
        mma16816(acc[1][0], al1, bh0);
        mma16816(acc[1][1], al1, bh0 + 2);
        mma16816(acc[1][2], al1, bh1);
        mma16816(acc[1][3], al1, bh1 + 2);
    }

    // ---- epilogue: floor(log2(m)) == IEEE exponent (exact for positive normals) ----
    const int rbase = fbase + m0w + (lane >> 2);
    const int cbase = n0w + (lane & 3) * 2;
    #pragma unroll
    for (int mb = 0; mb < 2; ++mb) {
        #pragma unroll
        for (int rr = 0; rr < 2; ++rr) {
            float* op = out + (size_t)(rbase + 16 * mb + 8 * rr) * NMELS + cbase;
            #pragma unroll
            for (int nb = 0; nb < 4; ++nb) {
                float2 r;
                r.x = (float)(((__float_as_int(acc[mb][nb][2 * rr + 0]) >> 23) & 255) - 127);
                r.y = (float)(((__float_as_int(acc[mb][nb][2 * rr + 1]) >> 23) & 255) - 127);
                *reinterpret_cast<float2*>(op + 8 * nb) = r;
            }
        }
    }
}

extern "C" void kernel_launch(void* const* d_in, const int* in_sizes, int n_in,
                              void* d_out, int out_size)
{
    const float* x  = (const float*)d_in[0];   // (256,256,512,1) fp32
    const float* fb = (const float*)d_in[1];   // (64,257) fp32
    float* out = (float*)d_out;                // (256,256,64,1) fp32

    cudaFuncSetAttribute(lmfe_hmma_kernel, cudaFuncAttributeMaxDynamicSharedMemorySize, SM_TOTAL);

    const int nframes = in_sizes[0] / FFT;     // 65536
    const int grid    = nframes / F_TILE;      // 512
    lmfe_hmma_kernel<<<grid, THREADS, SM_TOTAL>>>(x, fb, out);
}

// round 14
// speedup vs baseline: 2.8330x; 2.8330x over previous
#include <cuda_runtime.h>
#include <cstdint>

#define THREADS 256
#define F_TILE  128            // 8 warps x 16 frames
#define HALF    257
#define NMELS   64
#define FFT     512
#define PAIRS   136            // staged B k-pairs (KPAD=272)
#define STRIDE  280            // B smem row stride in bf16 (560B)

#define SM_BHI  0
#define SM_BLO  (NMELS * STRIDE * 2)            // 35840
#define SM_TOTAL (2 * NMELS * STRIDE * 2)       // 71680

__device__ __forceinline__ uint32_t smem_u32(const void* p) {
    uint32_t a;
    asm("{ .reg .u64 t; cvta.to.shared.u64 t, %1; cvt.u32.u64 %0, t; }" : "=r"(a) : "l"(p));
    return a;
}

// pack {first arg -> low half}
__device__ __forceinline__ uint32_t pack_bf16x2(float lo, float hi) {
    uint32_t r;
    asm("cvt.rn.bf16x2.f32 %0, %1, %2;" : "=r"(r) : "f"(hi), "f"(lo));
    return r;
}

__device__ __forceinline__ void ldsm_x4(uint32_t* r, uint32_t addr) {
    asm volatile("ldmatrix.sync.aligned.m8n8.x4.shared.b16 {%0,%1,%2,%3}, [%4];"
                 : "=r"(r[0]), "=r"(r[1]), "=r"(r[2]), "=r"(r[3]) : "r"(addr));
}

__device__ __forceinline__ void mma16816(float* c, const uint32_t* a, const uint32_t* b) {
    asm volatile(
        "mma.sync.aligned.m16n8k16.row.col.f32.bf16.bf16.f32 "
        "{%0,%1,%2,%3}, {%4,%5,%6,%7}, {%8,%9}, {%0,%1,%2,%3};"
        : "+f"(c[0]), "+f"(c[1]), "+f"(c[2]), "+f"(c[3])
        : "r"(a[0]), "r"(a[1]), "r"(a[2]), "r"(a[3]), "r"(b[0]), "r"(b[1]));
}

// mag = (v+1)^2 for a k-adjacent pair, then bf16 hi/lo split
__device__ __forceinline__ void mag_split(float2 v, uint32_t& hi, uint32_t& lo) {
    float t0 = v.x + 1.f, t1 = v.y + 1.f;
    float m0 = t0 * t0,  m1 = t1 * t1;
    hi = pack_bf16x2(m0, m1);
    float h0 = __uint_as_float(hi << 16);
    float h1 = __uint_as_float(hi & 0xFFFF0000u);
    lo = pack_bf16x2(m0 - h0, m1 - h1);
}

__device__ __forceinline__ void split_pair(float m0, float m1, uint32_t& hi, uint32_t& lo) {
    hi = pack_bf16x2(m0, m1);
    float h0 = __uint_as_float(hi << 16);
    float h1 = __uint_as_float(hi & 0xFFFF0000u);
    lo = pack_bf16x2(m0 - h0, m1 - h1);
}

__global__ __launch_bounds__(THREADS, 3)
void lmfe_hmma_kernel(const float* __restrict__ x, const float* __restrict__ fb,
                      float* __restrict__ out)
{
    extern __shared__ char smem[];
    const uint32_t smem_base = smem_u32(smem);
    const int tid   = threadIdx.x;
    const int wid   = tid >> 5;
    const int lane  = tid & 31;
    const int fbase = blockIdx.x * F_TILE;

    // ---- stage B only: fb split hi/lo, [n][k] K-major (col-major KxN for mma.row.col) ----
    for (int idx = tid; idx < NMELS * PAIRS; idx += THREADS) {
        int n = idx / PAIRS;
        int p = idx - n * PAIRS;
        float m0 = 0.f, m1 = 0.f;
        if (p < 128) {
            m0 = fb[n * HALF + 2 * p];
            m1 = fb[n * HALF + 2 * p + 1];
        } else if (p == 128) {
            m0 = fb[n * HALF + 256];
        }
        uint32_t hi, lo;
        split_pair(m0, m1, hi, lo);
        uint32_t off = (uint32_t)(n * STRIDE + 2 * p) * 2;
        *reinterpret_cast<uint32_t*>(smem + SM_BHI + off) = hi;
        *reinterpret_cast<uint32_t*>(smem + SM_BLO + off) = lo;
    }

    // ---- A pointers: lane-private rows of x (native K-major!) ----
    const int r  = lane >> 2;               // 0..7
    const int kc = (lane & 3) * 2;          // 0,2,4,6
    const float* p0 = x + (size_t)(fbase + wid * 16 + r) * FFT + kc;   // frame row r
    const float* p1 = p0 + 8 * FFT;                                    // frame row r+8

    // prefetch k-step 0
    float2 ra0 = *reinterpret_cast<const float2*>(p0);
    float2 ra1 = *reinterpret_cast<const float2*>(p1);
    float2 ra2 = *reinterpret_cast<const float2*>(p0 + 8);
    float2 ra3 = *reinterpret_cast<const float2*>(p1 + 8);

    __syncthreads();

    // ---- B ldmatrix lane address (k-invariant part), same mapping as validated r12 ----
    const uint32_t b_loff =
        (uint32_t)(((lane & 7) + ((lane >> 4) << 3)) * STRIDE * 2) +
        (((lane >> 3) & 1) << 4);
    const uint32_t bh = smem_base + SM_BHI + b_loff;
    const uint32_t bl = smem_base + SM_BLO + b_loff;
    const uint32_t NSTEP16 = 16u * STRIDE * 2;     // 16 mel rows

    float acc[8][4];
    #pragma unroll
    for (int nb = 0; nb < 8; ++nb)
        #pragma unroll
        for (int i = 0; i < 4; ++i) acc[nb][i] = 0.f;

    uint32_t bf[16];

    #pragma unroll 1
    for (int ks = 0; ks < 16; ++ks) {
        // convert current raw A -> hi/lo fragments
        uint32_t ahi[4], alo[4];
        mag_split(ra0, ahi[0], alo[0]);
        mag_split(ra1, ahi[1], alo[1]);
        mag_split(ra2, ahi[2], alo[2]);
        mag_split(ra3, ahi[3], alo[3]);

        // prefetch next k-step (ks=15 prefetches tail ks=16; in-bounds, masked later)
        {
            const float* q0 = p0 + (ks + 1) * 16;
            const float* q1 = p1 + (ks + 1) * 16;
            ra0 = *reinterpret_cast<const float2*>(q0);
            ra1 = *reinterpret_cast<const float2*>(q1);
            ra2 = *reinterpret_cast<const float2*>(q0 + 8);
            ra3 = *reinterpret_cast<const float2*>(q1 + 8);
        }

        const uint32_t koff = (uint32_t)ks * 32;
        // B hi: chains hh then lh
        ldsm_x4(bf + 0,  bh + koff);
        ldsm_x4(bf + 4,  bh + koff + NSTEP16);
        ldsm_x4(bf + 8,  bh + koff + 2 * NSTEP16);
        ldsm_x4(bf + 12, bh + koff + 3 * NSTEP16);
        #pragma unroll
        for (int nb = 0; nb < 8; ++nb) mma16816(acc[nb], ahi, bf + 2 * nb);
        #pragma unroll
        for (int nb = 0; nb < 8; ++nb) mma16816(acc[nb], alo, bf + 2 * nb);
        // B lo: chain hl
        ldsm_x4(bf + 0,  bl + koff);
        ldsm_x4(bf + 4,  bl + koff + NSTEP16);
        ldsm_x4(bf + 8,  bl + koff + 2 * NSTEP16);
        ldsm_x4(bf + 12, bl + koff + 3 * NSTEP16);
        #pragma unroll
        for (int nb = 0; nb < 8; ++nb) mma16816(acc[nb], ahi, bf + 2 * nb);
    }

    // ---- tail k-step 16: only k=256 is real (k=257..271 zero) ----
    {
        uint32_t ahi[4] = {0, 0, 0, 0}, alo[4] = {0, 0, 0, 0};
        if ((lane & 3) == 0) {
            float t0 = ra0.x + 1.f, m0 = t0 * t0;
            float t1 = ra1.x + 1.f, m1 = t1 * t1;
            split_pair(m0, 0.f, ahi[0], alo[0]);
            split_pair(m1, 0.f, ahi[1], alo[1]);
        }
        const uint32_t koff = 16u * 32;
        ldsm_x4(bf + 0,  bh + koff);
        ldsm_x4(bf + 4,  bh + koff + NSTEP16);
        ldsm_x4(bf + 8,  bh + koff + 2 * NSTEP16);
        ldsm_x4(bf + 12, bh + koff + 3 * NSTEP16);
        #pragma unroll
        for (int nb = 0; nb < 8; ++nb) mma16816(acc[nb], ahi, bf + 2 * nb);
        #pragma unroll
        for (int nb = 0; nb < 8; ++nb) mma16816(acc[nb], alo, bf + 2 * nb);
        ldsm_x4(bf + 0,  bl + koff);
        ldsm_x4(bf + 4,  bl + koff + NSTEP16);
        ldsm_x4(bf + 8,  bl + koff + 2 * NSTEP16);
        ldsm_x4(bf + 12, bl + koff + 3 * NSTEP16);
        #pragma unroll
        for (int nb = 0; nb < 8; ++nb) mma16816(acc[nb], ahi, bf + 2 * nb);
    }

    // ---- epilogue: floor(log2(m)) == IEEE exponent (exact for positive normals) ----
    // c frag: {c0,c1} row r, {c2,c3} row r+8; cols nb*8 + 2*(lane&3)
    const int frow = fbase + wid * 16 + r;
    const int cb   = (lane & 3) * 2;
    #pragma unroll
    for (int rr = 0; rr < 2; ++rr) {
        float* op = out + (size_t)(frow + 8 * rr) * NMELS + cb;
        #pragma unroll
        for (int nb = 0; nb < 8; ++nb) {
            float2 w;
            w.x = (float)(((__float_as_int(acc[nb][2 * rr + 0]) >> 23) & 255) - 127);
            w.y = (float)(((__float_as_int(acc[nb][2 * rr + 1]) >> 23) & 255) - 127);
            *reinterpret_cast<float2*>(op + 8 * nb) = w;
        }
    }
}

extern "C" void kernel_launch(void* const* d_in, const int* in_sizes, int n_in,
                              void* d_out, int out_size)
{
    const float* x  = (const float*)d_in[0];   // (256,256,512,1) fp32
    const float* fb = (const float*)d_in[1];   // (64,257) fp32
    float* out = (float*)d_out;                // (256,256,64,1) fp32

    cudaFuncSetAttribute(lmfe_hmma_kernel, cudaFuncAttributeMaxDynamicSharedMemorySize, SM_TOTAL);

    const int nframes = in_sizes[0] / FFT;     // 65536
    const int grid    = nframes / F_TILE;      // 512
    lmfe_hmma_kernel<<<grid, THREADS, SM_TOTAL>>>(x, fb, out);
}

// round 16
// speedup vs baseline: 5.2006x; 1.8357x over previous
#include <cuda_runtime.h>
#include <cstdint>

#define THREADS 256
#define F_TILE  256            // 8 warps x 32 frames
#define HALF    257
#define NMELS   64
#define FFT     512
#define PAIRS   136            // staged B k-pairs (KPAD=272)
#define STRIDE  280            // B smem row stride in bf16 (560B)

#define SM_BHI  0
#define SM_BLO  (NMELS * STRIDE * 2)            // 35840
#define SM_TOTAL (2 * NMELS * STRIDE * 2)       // 71680

__device__ __forceinline__ uint32_t smem_u32(const void* p) {
    uint32_t a;
    asm("{ .reg .u64 t; cvta.to.shared.u64 t, %1; cvt.u32.u64 %0, t; }" : "=r"(a) : "l"(p));
    return a;
}

__device__ __forceinline__ uint32_t pack_bf16x2(float lo, float hi) {
    uint32_t r;
    asm("cvt.rn.bf16x2.f32 %0, %1, %2;" : "=r"(r) : "f"(hi), "f"(lo));
    return r;
}

__device__ __forceinline__ void ldsm_x4(uint32_t* r, uint32_t addr) {
    asm volatile("ldmatrix.sync.aligned.m8n8.x4.shared.b16 {%0,%1,%2,%3}, [%4];"
                 : "=r"(r[0]), "=r"(r[1]), "=r"(r[2]), "=r"(r[3]) : "r"(addr));
}

__device__ __forceinline__ void mma16816(float* c, const uint32_t* a, const uint32_t* b) {
    asm volatile(
        "mma.sync.aligned.m16n8k16.row.col.f32.bf16.bf16.f32 "
        "{%0,%1,%2,%3}, {%4,%5,%6,%7}, {%8,%9}, {%0,%1,%2,%3};"
        : "+f"(c[0]), "+f"(c[1]), "+f"(c[2]), "+f"(c[3])
        : "r"(a[0]), "r"(a[1]), "r"(a[2]), "r"(a[3]), "r"(b[0]), "r"(b[1]));
}

__device__ __forceinline__ void mag_split(float2 v, uint32_t& hi, uint32_t& lo) {
    float t0 = v.x + 1.f, t1 = v.y + 1.f;
    float m0 = t0 * t0,  m1 = t1 * t1;
    hi = pack_bf16x2(m0, m1);
    float h0 = __uint_as_float(hi << 16);
    float h1 = __uint_as_float(hi & 0xFFFF0000u);
    lo = pack_bf16x2(m0 - h0, m1 - h1);
}

__device__ __forceinline__ void split_pair(float m0, float m1, uint32_t& hi, uint32_t& lo) {
    hi = pack_bf16x2(m0, m1);
    float h0 = __uint_as_float(hi << 16);
    float h1 = __uint_as_float(hi & 0xFFFF0000u);
    lo = pack_bf16x2(m0 - h0, m1 - h1);
}

__global__ __launch_bounds__(THREADS, 2)
void lmfe_hmma_kernel(const float* __restrict__ x, const float* __restrict__ fb,
                      float* __restrict__ out)
{
    extern __shared__ char smem[];
    const uint32_t smem_base = smem_u32(smem);
    const int tid   = threadIdx.x;
    const int wid   = tid >> 5;
    const int lane  = tid & 31;
    const int fbase = blockIdx.x * F_TILE;

    // ---- stage B: fb split hi/lo, [n][k] K-major (col-major KxN for mma.row.col) ----
    for (int idx = tid; idx < NMELS * PAIRS; idx += THREADS) {
        int n = idx / PAIRS;
        int p = idx - n * PAIRS;
        float m0 = 0.f, m1 = 0.f;
        if (p < 128) {
            m0 = fb[n * HALF + 2 * p];
            m1 = fb[n * HALF + 2 * p + 1];
        } else if (p == 128) {
            m0 = fb[n * HALF + 256];
        }
        uint32_t hi, lo;
        split_pair(m0, m1, hi, lo);
        uint32_t off = (uint32_t)(n * STRIDE + 2 * p) * 2;
        *reinterpret_cast<uint32_t*>(smem + SM_BHI + off) = hi;
        *reinterpret_cast<uint32_t*>(smem + SM_BLO + off) = lo;
    }

    // ---- A pointers: 4 lane-private rows of x (m32 warp tile, native K-major) ----
    const int r  = lane >> 2;               // 0..7
    const int kc = (lane & 3) * 2;          // 0,2,4,6
    const float* p0 = x + (size_t)(fbase + wid * 32 + r) * FFT + kc;   // row r
    const float* p1 = p0 +  8 * FFT;                                   // row r+8
    const float* p2 = p0 + 16 * FFT;                                   // row r+16
    const float* p3 = p0 + 24 * FFT;                                   // row r+24

    // prefetch k-step 0: ra[blk][0]=k lo-half, ra[blk][1]=k+8 half; blk0=(r,r+8), blk1=(r+16,r+24)
    float2 ra[8];
    ra[0] = *reinterpret_cast<const float2*>(p0);
    ra[1] = *reinterpret_cast<const float2*>(p1);
    ra[2] = *reinterpret_cast<const float2*>(p0 + 8);
    ra[3] = *reinterpret_cast<const float2*>(p1 + 8);
    ra[4] = *reinterpret_cast<const float2*>(p2);
    ra[5] = *reinterpret_cast<const float2*>(p3);
    ra[6] = *reinterpret_cast<const float2*>(p2 + 8);
    ra[7] = *reinterpret_cast<const float2*>(p3 + 8);

    __syncthreads();

    // ---- B ldmatrix lane address (k-invariant), identical mapping to validated r12/r14 ----
    const uint32_t b_loff =
        (uint32_t)(((lane & 7) + ((lane >> 4) << 3)) * STRIDE * 2) +
        (((lane >> 3) & 1) << 4);
    const uint32_t bh = smem_base + SM_BHI + b_loff;
    const uint32_t bl = smem_base + SM_BLO + b_loff;
    const uint32_t NSTEP16 = 16u * STRIDE * 2;

    float acc[2][8][4];
    #pragma unroll
    for (int mb = 0; mb < 2; ++mb)
        #pragma unroll
        for (int nb = 0; nb < 8; ++nb)
            #pragma unroll
            for (int i = 0; i < 4; ++i) acc[mb][nb][i] = 0.f;

    uint32_t bf[16];

    #pragma unroll 1
    for (int ks = 0; ks < 16; ++ks) {
        // convert current A (8 pairs -> 2 m-block hi/lo fragments)
        uint32_t ahi[8], alo[8];
        #pragma unroll
        for (int i = 0; i < 8; ++i) mag_split(ra[i], ahi[i], alo[i]);

        // prefetch next k-step (ks=15 loads tail k=256..263, in-bounds)
        {
            const float* q0 = p0 + (ks + 1) * 16;
            const float* q1 = p1 + (ks + 1) * 16;
            const float* q2 = p2 + (ks + 1) * 16;
            const float* q3 = p3 + (ks + 1) * 16;
            ra[0] = *reinterpret_cast<const float2*>(q0);
            ra[1] = *reinterpret_cast<const float2*>(q1);
            ra[2] = *reinterpret_cast<const float2*>(q0 + 8);
            ra[3] = *reinterpret_cast<const float2*>(q1 + 8);
            ra[4] = *reinterpret_cast<const float2*>(q2);
            ra[5] = *reinterpret_cast<const float2*>(q3);
            ra[6] = *reinterpret_cast<const float2*>(q2 + 8);
            ra[7] = *reinterpret_cast<const float2*>(q3 + 8);
        }

        const uint32_t koff = (uint32_t)ks * 32;
        // B hi: chains hh + lh (bh fragments feed 32 MMA)
        ldsm_x4(bf + 0,  bh + koff);
        ldsm_x4(bf + 4,  bh + koff + NSTEP16);
        ldsm_x4(bf + 8,  bh + koff + 2 * NSTEP16);
        ldsm_x4(bf + 12, bh + koff + 3 * NSTEP16);
        #pragma unroll
        for (int nb = 0; nb < 8; ++nb) {
            mma16816(acc[0][nb], ahi,     bf + 2 * nb);
            mma16816(acc[1][nb], ahi + 4, bf + 2 * nb);
        }
        #pragma unroll
        for (int nb = 0; nb < 8; ++nb) {
            mma16816(acc[0][nb], alo,     bf + 2 * nb);
            mma16816(acc[1][nb], alo + 4, bf + 2 * nb);
        }
        // B lo: chain hl (16 MMA)
        ldsm_x4(bf + 0,  bl + koff);
        ldsm_x4(bf + 4,  bl + koff + NSTEP16);
        ldsm_x4(bf + 8,  bl + koff + 2 * NSTEP16);
        ldsm_x4(bf + 12, bl + koff + 3 * NSTEP16);
        #pragma unroll
        for (int nb = 0; nb < 8; ++nb) {
            mma16816(acc[0][nb], ahi,     bf + 2 * nb);
            mma16816(acc[1][nb], ahi + 4, bf + 2 * nb);
        }
    }

    // ---- tail k-step 16: only k=256 real ----
    {
        uint32_t ahi[8], alo[8];
        #pragma unroll
        for (int i = 0; i < 8; ++i) { ahi[i] = 0u; alo[i] = 0u; }
        if ((lane & 3) == 0) {
            #pragma unroll
            for (int i = 0; i < 2; ++i) {      // ra[0],ra[1] (blk0) ; ra[4],ra[5] (blk1)
                float t0 = ra[i].x + 1.f,     m0 = t0 * t0;
                float t1 = ra[i + 4].x + 1.f, m1 = t1 * t1;
                split_pair(m0, 0.f, ahi[i],     alo[i]);
                split_pair(m1, 0.f, ahi[i + 4], alo[i + 4]);
            }
        }
        const uint32_t koff = 16u * 32;
        ldsm_x4(bf + 0,  bh + koff);
        ldsm_x4(bf + 4,  bh + koff + NSTEP16);
        ldsm_x4(bf + 8,  bh + koff + 2 * NSTEP16);
        ldsm_x4(bf + 12, bh + koff + 3 * NSTEP16);
        #pragma unroll
        for (int nb = 0; nb < 8; ++nb) {
            mma16816(acc[0][nb], ahi,     bf + 2 * nb);
            mma16816(acc[1][nb], ahi + 4, bf + 2 * nb);
        }
        #pragma unroll
        for (int nb = 0; nb < 8; ++nb) {
            mma16816(acc[0][nb], alo,     bf + 2 * nb);
            mma16816(acc[1][nb], alo + 4, bf + 2 * nb);
        }
        ldsm_x4(bf + 0,  bl + koff);
        ldsm_x4(bf + 4,  bl + koff + NSTEP16);
        ldsm_x4(bf + 8,  bl + koff + 2 * NSTEP16);
        ldsm_x4(bf + 12, bl + koff + 3 * NSTEP16);
        #pragma unroll
        for (int nb = 0; nb < 8; ++nb) {
            mma16816(acc[0][nb], ahi,     bf + 2 * nb);
            mma16816(acc[1][nb], ahi + 4, bf + 2 * nb);
        }
    }

    // ---- epilogue: floor(log2(m)) == IEEE exponent (exact for positive normals) ----
    const int frow = fbase + wid * 32 + r;
    const int cb   = (lane & 3) * 2;
    #pragma unroll
    for (int mb = 0; mb < 2; ++mb) {
        #pragma unroll
        for (int rr = 0; rr < 2; ++rr) {
            float* op = out + (size_t)(frow + 16 * mb + 8 * rr) * NMELS + cb;
            #pragma unroll
            for (int nb = 0; nb < 8; ++nb) {
                float2 w;
                w.x = (float)(((__float_as_int(acc[mb][nb][2 * rr + 0]) >> 23) & 255) - 127);
                w.y = (float)(((__float_as_int(acc[mb][nb][2 * rr + 1]) >> 23) & 255) - 127);
                *reinterpret_cast<float2*>(op + 8 * nb) = w;
            }
        }
    }
}

extern "C" void kernel_launch(void* const* d_in, const int* in_sizes, int n_in,
                              void* d_out, int out_size)
{
    const float* x  = (const float*)d_in[0];   // (256,256,512,1) fp32
    const float* fb = (const float*)d_in[1];   // (64,257) fp32
    float* out = (float*)d_out;                // (256,256,64,1) fp32

    cudaFuncSetAttribute(lmfe_hmma_kernel, cudaFuncAttributeMaxDynamicSharedMemorySize, SM_TOTAL);

    const int nframes = in_sizes[0] / FFT;     // 65536
    const int grid    = nframes / F_TILE;      // 256
    lmfe_hmma_kernel<<<grid, THREADS, SM_TOTAL>>>(x, fb, out);
}